// round 11
// baseline (speedup 1.0000x reference)
#include <cuda_runtime.h>
#include <math.h>

#define NMAX 50000
#define EMAX 800000
#define DF   96
// scan: 256 threads x 4 elems = 1024 elems per block
#define SCAN_T 256
#define SCAN_E 1024
#define CHAIN_B 148          // persistent chain kernel blocks (1 per SM)

// Scratch (allocation-free: __device__ globals). 16B-aligned for int4 access.
__device__ __align__(16) float g_h[NMAX * DF];     // projected features
__device__ __align__(16) int   g_cnt[NMAX];        // per-row degree (zero at entry)
__device__ __align__(16) int   g_offs[NMAX + 4];   // CSR offsets (padded)
__device__ __align__(16) int   g_cur[NMAX];        // scatter cursors
__device__ int g_part_in[64];                      // scan partials (phase2 -> phase3)
__device__ int g_part_out[64];                     // exclusive partials (phase3 -> phase4)
__device__ unsigned g_bc[4];                       // grid-barrier counters (zero at entry)
__device__ __align__(16) int2  g_e[EMAX];          // packed (col, w-bits) per slot

// ---------------- grid barrier (counter + spin; reset by gather) ---------
__device__ __forceinline__ void gridbar(int p) {
    __syncthreads();
    if (threadIdx.x == 0) {
        __threadfence();
        atomicAdd(&g_bc[p], 1u);
        while (atomicAdd(&g_bc[p], 0u) < (unsigned)CHAIN_B) { }
    }
    __syncthreads();
}

// ---------------- dense projection: h = x @ W + b ----------------
// blockDim = (32, 8). Block tile: 32 rows x 96 cols. Thread: 4 rows x 3 cols.
__global__ void gemm_kernel(const float* __restrict__ x,
                            const float* __restrict__ W,
                            const float* __restrict__ b,
                            int N) {
    __shared__ float Ws[DF * DF];      // 36 KB
    __shared__ float xs[32][DF];       // 12 KB

    const int tx  = threadIdx.x;
    const int ty  = threadIdx.y;
    const int tid = ty * 32 + tx;

    for (int i = tid; i < DF * DF; i += 256) Ws[i] = W[i];

    const float b0 = b[tx];
    const float b1 = b[tx + 32];
    const float b2 = b[tx + 64];

    const int tile = blockIdx.x * 32;
    if (tile >= N) return;

    for (int i = tid; i < 32 * DF; i += 256) {
        int r = i / DF, c = i % DF;
        int gr = tile + r;
        xs[r][c] = (gr < N) ? x[(size_t)gr * DF + c] : 0.0f;
    }
    __syncthreads();

    const int r0 = ty * 4;
    float a[4][3];
#pragma unroll
    for (int j = 0; j < 4; j++) { a[j][0] = 0.f; a[j][1] = 0.f; a[j][2] = 0.f; }

#pragma unroll 4
    for (int k = 0; k < DF; k++) {
        float w0 = Ws[k * DF + tx];
        float w1 = Ws[k * DF + tx + 32];
        float w2 = Ws[k * DF + tx + 64];
#pragma unroll
        for (int j = 0; j < 4; j++) {
            float xv = xs[r0 + j][k];
            a[j][0] = fmaf(xv, w0, a[j][0]);
            a[j][1] = fmaf(xv, w1, a[j][1]);
            a[j][2] = fmaf(xv, w2, a[j][2]);
        }
    }

#pragma unroll
    for (int j = 0; j < 4; j++) {
        int gr = tile + r0 + j;
        if (gr < N) {
            float* hp = &g_h[(size_t)gr * DF];
            hp[tx]      = a[j][0] + b0;
            hp[tx + 32] = a[j][1] + b1;
            hp[tx + 64] = a[j][2] + b2;
        }
    }
}

// ---------------- fused edge chain: hist | scan | scatter ----------------
// One persistent kernel, 148 blocks x 256 threads, 4 grid barriers.
// g_cnt and g_bc are zero on entry (module-load init; restored each call:
// g_cnt by phase 4, g_bc by the gather kernel).
__global__ void __launch_bounds__(256, 8)
chain_kernel(const int* __restrict__ row,
             const int* __restrict__ col,
             const float* __restrict__ w,
             int n, int E) {
    __shared__ int warpsum[8];

    const int bid = blockIdx.x;
    const int tid = threadIdx.x;
    const int gtid = bid * 256 + tid;
    const int gstride = CHAIN_B * 256;

    // ---- phase 1: degree histogram (int4) ----
    {
        const int E4 = E >> 2;
        const int4* r4 = (const int4*)row;
        for (int i = gtid; i < E4; i += gstride) {
            int4 v = r4[i];
            atomicAdd(&g_cnt[v.x], 1);
            atomicAdd(&g_cnt[v.y], 1);
            atomicAdd(&g_cnt[v.z], 1);
            atomicAdd(&g_cnt[v.w], 1);
        }
        for (int i = (E4 << 2) + gtid; i < E; i += gstride)
            atomicAdd(&g_cnt[row[i]], 1);
    }
    gridbar(0);

    // ---- phase 2: block-local exclusive scan (blocks < nScan) ----
    const int nScan = (n + SCAN_E - 1) / SCAN_E;   // <= 49 <= 64
    if (bid < nScan) {
        const int lane = tid & 31;
        const int wid  = tid >> 5;
        const int e0   = bid * SCAN_E + tid * 4;

        int4 v;
        v.x = (e0     < n) ? g_cnt[e0]     : 0;
        v.y = (e0 + 1 < n) ? g_cnt[e0 + 1] : 0;
        v.z = (e0 + 2 < n) ? g_cnt[e0 + 2] : 0;
        v.w = (e0 + 3 < n) ? g_cnt[e0 + 3] : 0;
        const int tsum = v.x + v.y + v.z + v.w;

        int inc = tsum;
#pragma unroll
        for (int d = 1; d < 32; d <<= 1) {
            int t = __shfl_up_sync(0xFFFFFFFFu, inc, d);
            if (lane >= d) inc += t;
        }
        if (lane == 31) warpsum[wid] = inc;
        __syncthreads();
        if (tid < 8) {
            int ws = warpsum[tid];
#pragma unroll
            for (int d = 1; d < 8; d <<= 1) {
                int t = __shfl_up_sync(0xFFu, ws, d);
                if ((tid & 7) >= d) ws += t;
            }
            warpsum[tid] = ws;
        }
        __syncthreads();

        const int base = ((wid > 0) ? warpsum[wid - 1] : 0) + inc - tsum;

        if (e0 + 3 < n) {
            int4 o;
            o.x = base;
            o.y = base + v.x;
            o.z = o.y + v.y;
            o.w = o.z + v.z;
            *(int4*)&g_offs[e0] = o;
        } else {
            int run = base;
            if (e0     < n) { g_offs[e0]     = run; run += v.x; }
            if (e0 + 1 < n) { g_offs[e0 + 1] = run; run += v.y; }
            if (e0 + 2 < n) { g_offs[e0 + 2] = run; run += v.z; }
            if (e0 + 3 < n) { g_offs[e0 + 3] = run; }
        }
        if (tid == SCAN_T - 1) g_part_in[bid] = warpsum[7];
    }
    gridbar(1);

    // ---- phase 3: single-warp exclusive scan of <=64 partials ----
    if (bid == 0 && tid < 32) {
        const int i0 = 2 * tid, i1 = 2 * tid + 1;
        int a = (i0 < nScan) ? g_part_in[i0] : 0;
        int b = (i1 < nScan) ? g_part_in[i1] : 0;
        int s = a + b;
        int inc = s;
#pragma unroll
        for (int d = 1; d < 32; d <<= 1) {
            int t = __shfl_up_sync(0xFFFFFFFFu, inc, d);
            if (tid >= d) inc += t;
        }
        const int exc = inc - s;
        g_part_out[i0] = exc;
        g_part_out[i1] = exc + a;
    }
    gridbar(2);

    // ---- phase 4: add base, init cursors, re-zero cnt ----
    if (bid < nScan) {
        const int e0   = bid * SCAN_E + tid * 4;
        const int base = g_part_out[bid];
        const int4 z   = make_int4(0, 0, 0, 0);

        if (e0 + 3 < n) {
            int4 o = *(const int4*)&g_offs[e0];
            o.x += base; o.y += base; o.z += base; o.w += base;
            *(int4*)&g_offs[e0] = o;
            *(int4*)&g_cur[e0]  = o;
            *(int4*)&g_cnt[e0]  = z;
        } else {
#pragma unroll
            for (int j = 0; j < 4; j++) {
                int i = e0 + j;
                if (i < n) {
                    int o = g_offs[i] + base;
                    g_offs[i] = o;
                    g_cur[i]  = o;
                    g_cnt[i]  = 0;
                }
            }
        }
        if (e0 == 0) g_offs[n] = E;
    }
    gridbar(3);

    // ---- phase 5: bucket scatter into CSR slots (int4 reads) ----
    {
        const int E4 = E >> 2;
        const int4*   r4 = (const int4*)row;
        const int4*   c4 = (const int4*)col;
        const float4* w4 = (const float4*)w;
        for (int i = gtid; i < E4; i += gstride) {
            int4   r = r4[i];
            int4   c = c4[i];
            float4 wv = w4[i];
            int p;
            p = atomicAdd(&g_cur[r.x], 1); g_e[p] = make_int2(c.x, __float_as_int(wv.x));
            p = atomicAdd(&g_cur[r.y], 1); g_e[p] = make_int2(c.y, __float_as_int(wv.y));
            p = atomicAdd(&g_cur[r.z], 1); g_e[p] = make_int2(c.z, __float_as_int(wv.z));
            p = atomicAdd(&g_cur[r.w], 1); g_e[p] = make_int2(c.w, __float_as_int(wv.w));
        }
        for (int i = (E4 << 2) + gtid; i < E; i += gstride) {
            int p = atomicAdd(&g_cur[row[i]], 1);
            g_e[p] = make_int2(col[i], __float_as_int(w[i]));
        }
    }
}

// ---------------- warp-per-row gather + ELU ----------------
__global__ void gather_kernel(float* __restrict__ out, int N) {
    // reset chain-kernel barrier counters for the next replay
    if (blockIdx.x == 0 && threadIdx.x < 4) g_bc[threadIdx.x] = 0u;

    const int gwarp = (blockIdx.x * blockDim.x + threadIdx.x) >> 5;
    const int lane  = threadIdx.x & 31;
    if (gwarp >= N) return;

    const int s = g_offs[gwarp];
    const int e = g_offs[gwarp + 1];

    float a0 = 0.f, a1 = 0.f, a2 = 0.f;
    int i = s;

    // head: align i to even so int4 pair-loads of g_e are 16B-aligned
    if ((i & 1) && i < e) {
        const int2 e0 = g_e[i];
        const float wv = __int_as_float(e0.y);
        const float* hp = &g_h[(size_t)e0.x * DF];
        a0 = fmaf(wv, hp[lane],      a0);
        a1 = fmaf(wv, hp[lane + 32], a1);
        a2 = fmaf(wv, hp[lane + 64], a2);
        i++;
    }
    for (; i + 3 < e; i += 4) {
        const int4 pa = *(const int4*)&g_e[i];       // edges i, i+1
        const int4 pb = *(const int4*)&g_e[i + 2];   // edges i+2, i+3
        const float* h0 = &g_h[(size_t)pa.x * DF];
        const float* h1 = &g_h[(size_t)pa.z * DF];
        const float* h2 = &g_h[(size_t)pb.x * DF];
        const float* h3 = &g_h[(size_t)pb.z * DF];
        float p00 = h0[lane], p01 = h0[lane + 32], p02 = h0[lane + 64];
        float p10 = h1[lane], p11 = h1[lane + 32], p12 = h1[lane + 64];
        float p20 = h2[lane], p21 = h2[lane + 32], p22 = h2[lane + 64];
        float p30 = h3[lane], p31 = h3[lane + 32], p32 = h3[lane + 64];
        const float w0 = __int_as_float(pa.y);
        const float w1 = __int_as_float(pa.w);
        const float w2 = __int_as_float(pb.y);
        const float w3 = __int_as_float(pb.w);
        a0 = fmaf(w0, p00, a0); a1 = fmaf(w0, p01, a1); a2 = fmaf(w0, p02, a2);
        a0 = fmaf(w1, p10, a0); a1 = fmaf(w1, p11, a1); a2 = fmaf(w1, p12, a2);
        a0 = fmaf(w2, p20, a0); a1 = fmaf(w2, p21, a1); a2 = fmaf(w2, p22, a2);
        a0 = fmaf(w3, p30, a0); a1 = fmaf(w3, p31, a1); a2 = fmaf(w3, p32, a2);
    }
    for (; i < e; i++) {
        const int2 e0 = g_e[i];
        const float wv = __int_as_float(e0.y);
        const float* hp = &g_h[(size_t)e0.x * DF];
        a0 = fmaf(wv, hp[lane],      a0);
        a1 = fmaf(wv, hp[lane + 32], a1);
        a2 = fmaf(wv, hp[lane + 64], a2);
    }

    float* pre = out;
    float* act = out + (size_t)N * DF;
    const int o = gwarp * DF + lane;
    pre[o]      = a0;
    pre[o + 32] = a1;
    pre[o + 64] = a2;
    act[o]      = (a0 > 0.f) ? a0 : expm1f(a0);
    act[o + 32] = (a1 > 0.f) ? a1 : expm1f(a1);
    act[o + 64] = (a2 > 0.f) ? a2 : expm1f(a2);
}

// ---------------- launch ----------------
extern "C" void kernel_launch(void* const* d_in, const int* in_sizes, int n_in,
                              void* d_out, int out_size) {
    const float* x  = (const float*)d_in[0];
    const float* W  = (const float*)d_in[1];
    const float* b  = (const float*)d_in[2];
    const int*   ei = (const int*)d_in[3];
    const float* ew = (const float*)d_in[4];
    float* out = (float*)d_out;

    const int N = in_sizes[0] / DF;
    const int E = in_sizes[4];
    const int* row = ei;         // edge_index[0]
    const int* col = ei + E;     // edge_index[1]

    // One-time side-stream + events (created during the uncaptured
    // correctness call; no device memory allocated anywhere).
    static cudaStream_t s_side = nullptr;
    static cudaEvent_t  ev_fork = nullptr, ev_join = nullptr;
    if (s_side == nullptr) {
        cudaStreamCreateWithFlags(&s_side, cudaStreamNonBlocking);
        cudaEventCreateWithFlags(&ev_fork, cudaEventDisableTiming);
        cudaEventCreateWithFlags(&ev_join, cudaEventDisableTiming);
    }

    // Fork: GEMM on side stream, concurrent with the fused edge chain.
    cudaEventRecord(ev_fork, 0);
    cudaStreamWaitEvent(s_side, ev_fork, 0);
    dim3 gblk(32, 8);
    gemm_kernel<<<(N + 31) / 32, gblk, 0, s_side>>>(x, W, b, N);
    cudaEventRecord(ev_join, s_side);

    // Fused edge chain (hist | scan | scatter) on the main stream.
    chain_kernel<<<CHAIN_B, 256>>>(row, col, ew, N, E);

    // Join: gather needs both g_h (GEMM) and the CSR (chain).
    cudaStreamWaitEvent(0, ev_join, 0);
    const int threads = 256;
    gather_kernel<<<((size_t)N * 32 + threads - 1) / threads, threads>>>(out, N);
}

// round 12
// speedup vs baseline: 1.4337x; 1.4337x over previous
#include <cuda_runtime.h>
#include <math.h>

#define NMAX 50000
#define EMAX 800000
#define DF   96
// alloc: 256 threads x 4 elems = 1024 elems per block
#define SCAN_T 256
#define SCAN_E 1024

// Scratch (allocation-free: __device__ globals). 16B-aligned for int4 access.
__device__ __align__(16) float g_h[NMAX * DF];     // projected features
__device__ __align__(16) int   g_cnt[NMAX];        // per-row degree (zero at entry)
__device__ __align__(16) int   g_start[NMAX];      // row slot-range start
__device__ __align__(16) int   g_len[NMAX];        // row slot-range length
__device__ __align__(16) int   g_cur[NMAX];        // scatter cursors
__device__ int g_total;                            // global slot allocator (zero at entry)
__device__ __align__(16) int2  g_e[EMAX];          // packed (col, w-bits) per slot

// ---------------- dense projection: h = x @ W + b ----------------
// blockDim = (32, 8). Block tile: 32 rows x 96 cols. Thread: 4 rows x 3 cols.
__global__ void gemm_kernel(const float* __restrict__ x,
                            const float* __restrict__ W,
                            const float* __restrict__ b,
                            int N) {
    __shared__ float Ws[DF * DF];      // 36 KB
    __shared__ float xs[32][DF];       // 12 KB

    const int tx  = threadIdx.x;
    const int ty  = threadIdx.y;
    const int tid = ty * 32 + tx;

    for (int i = tid; i < DF * DF; i += 256) Ws[i] = W[i];

    const float b0 = b[tx];
    const float b1 = b[tx + 32];
    const float b2 = b[tx + 64];

    const int tile = blockIdx.x * 32;
    if (tile >= N) return;

    for (int i = tid; i < 32 * DF; i += 256) {
        int r = i / DF, c = i % DF;
        int gr = tile + r;
        xs[r][c] = (gr < N) ? x[(size_t)gr * DF + c] : 0.0f;
    }
    __syncthreads();

    const int r0 = ty * 4;
    float a[4][3];
#pragma unroll
    for (int j = 0; j < 4; j++) { a[j][0] = 0.f; a[j][1] = 0.f; a[j][2] = 0.f; }

#pragma unroll 4
    for (int k = 0; k < DF; k++) {
        float w0 = Ws[k * DF + tx];
        float w1 = Ws[k * DF + tx + 32];
        float w2 = Ws[k * DF + tx + 64];
#pragma unroll
        for (int j = 0; j < 4; j++) {
            float xv = xs[r0 + j][k];
            a[j][0] = fmaf(xv, w0, a[j][0]);
            a[j][1] = fmaf(xv, w1, a[j][1]);
            a[j][2] = fmaf(xv, w2, a[j][2]);
        }
    }

#pragma unroll
    for (int j = 0; j < 4; j++) {
        int gr = tile + r0 + j;
        if (gr < N) {
            float* hp = &g_h[(size_t)gr * DF];
            hp[tx]      = a[j][0] + b0;
            hp[tx + 32] = a[j][1] + b1;
            hp[tx + 64] = a[j][2] + b2;
        }
    }
}

// ---------------- degree histogram (int4 vectorized) ----------------
// g_cnt is zero on entry (module-load init / restored by alloc each call).
__global__ void hist_kernel(const int* __restrict__ row, int E) {
    const int E4 = E >> 2;
    const int4* r4 = (const int4*)row;
    for (int i = blockIdx.x * blockDim.x + threadIdx.x; i < E4;
         i += gridDim.x * blockDim.x) {
        int4 v = r4[i];
        atomicAdd(&g_cnt[v.x], 1);
        atomicAdd(&g_cnt[v.y], 1);
        atomicAdd(&g_cnt[v.z], 1);
        atomicAdd(&g_cnt[v.w], 1);
    }
    for (int i = (E4 << 2) + blockIdx.x * blockDim.x + threadIdx.x; i < E;
         i += gridDim.x * blockDim.x) {
        atomicAdd(&g_cnt[row[i]], 1);
    }
}

// ---------------- slot allocation: block scan + one global atomicAdd -----
// Replaces the ordered exclusive scan: row ranges are (start, len) with
// bases handed out per block by a single atomic counter. Order across
// blocks is irrelevant to correctness. Also re-zeroes g_cnt.
__global__ void alloc_kernel(int n) {
    __shared__ int warpsum[8];
    __shared__ int s_base;
    const int tid  = threadIdx.x;            // 0..255
    const int lane = tid & 31;
    const int wid  = tid >> 5;
    const int e0   = blockIdx.x * SCAN_E + tid * 4;

    int4 v;
    v.x = (e0     < n) ? g_cnt[e0]     : 0;
    v.y = (e0 + 1 < n) ? g_cnt[e0 + 1] : 0;
    v.z = (e0 + 2 < n) ? g_cnt[e0 + 2] : 0;
    v.w = (e0 + 3 < n) ? g_cnt[e0 + 3] : 0;
    const int tsum = v.x + v.y + v.z + v.w;

    // warp inclusive scan of per-thread sums
    int inc = tsum;
#pragma unroll
    for (int d = 1; d < 32; d <<= 1) {
        int t = __shfl_up_sync(0xFFFFFFFFu, inc, d);
        if (lane >= d) inc += t;
    }
    if (lane == 31) warpsum[wid] = inc;
    __syncthreads();
    if (tid < 8) {
        int ws = warpsum[tid];
#pragma unroll
        for (int d = 1; d < 8; d <<= 1) {
            int t = __shfl_up_sync(0xFFu, ws, d);
            if ((tid & 7) >= d) ws += t;
        }
        warpsum[tid] = ws;
    }
    __syncthreads();

    if (tid == 0) s_base = atomicAdd(&g_total, warpsum[7]);  // block base
    __syncthreads();

    const int base = s_base + ((wid > 0) ? warpsum[wid - 1] : 0) + inc - tsum;
    const int4 z = make_int4(0, 0, 0, 0);

    if (e0 + 3 < n) {
        int4 o;
        o.x = base;
        o.y = base + v.x;
        o.z = o.y + v.y;
        o.w = o.z + v.z;
        *(int4*)&g_start[e0] = o;
        *(int4*)&g_cur[e0]   = o;
        *(int4*)&g_len[e0]   = v;
        *(int4*)&g_cnt[e0]   = z;        // restore invariant for next call
    } else {
        int run = base;
#pragma unroll
        for (int j = 0; j < 4; j++) {
            int i = e0 + j;
            int c = (j == 0) ? v.x : (j == 1) ? v.y : (j == 2) ? v.z : v.w;
            if (i < n) {
                g_start[i] = run;
                g_cur[i]   = run;
                g_len[i]   = c;
                g_cnt[i]   = 0;
                run += c;
            }
        }
    }
}

// ---------------- bucket scatter into CSR slots (vectorized reads) -------
__global__ void scatter_kernel(const int* __restrict__ row,
                               const int* __restrict__ col,
                               const float* __restrict__ w, int E) {
    const int E4 = E >> 2;
    const int4*   r4 = (const int4*)row;
    const int4*   c4 = (const int4*)col;
    const float4* w4 = (const float4*)w;
    for (int i = blockIdx.x * blockDim.x + threadIdx.x; i < E4;
         i += gridDim.x * blockDim.x) {
        int4   r = r4[i];
        int4   c = c4[i];
        float4 wv = w4[i];
        int p;
        p = atomicAdd(&g_cur[r.x], 1); g_e[p] = make_int2(c.x, __float_as_int(wv.x));
        p = atomicAdd(&g_cur[r.y], 1); g_e[p] = make_int2(c.y, __float_as_int(wv.y));
        p = atomicAdd(&g_cur[r.z], 1); g_e[p] = make_int2(c.z, __float_as_int(wv.z));
        p = atomicAdd(&g_cur[r.w], 1); g_e[p] = make_int2(c.w, __float_as_int(wv.w));
    }
    for (int i = (E4 << 2) + blockIdx.x * blockDim.x + threadIdx.x; i < E;
         i += gridDim.x * blockDim.x) {
        int p = atomicAdd(&g_cur[row[i]], 1);
        g_e[p] = make_int2(col[i], __float_as_int(w[i]));
    }
}

// ---------------- warp-per-row gather + ELU (int4 pair loads) ----------
__global__ void gather_kernel(float* __restrict__ out, int N) {
    // reset slot allocator for the next replay (not read by this kernel)
    if (blockIdx.x == 0 && threadIdx.x == 0) g_total = 0;

    const int gwarp = (blockIdx.x * blockDim.x + threadIdx.x) >> 5;
    const int lane  = threadIdx.x & 31;
    if (gwarp >= N) return;

    const int s = g_start[gwarp];
    const int e = s + g_len[gwarp];

    float a0 = 0.f, a1 = 0.f, a2 = 0.f;
    int i = s;

    // head: align i to even so int4 pair-loads of g_e are 16B-aligned
    if ((i & 1) && i < e) {
        const int2 e0 = g_e[i];
        const float wv = __int_as_float(e0.y);
        const float* hp = &g_h[(size_t)e0.x * DF];
        a0 = fmaf(wv, hp[lane],      a0);
        a1 = fmaf(wv, hp[lane + 32], a1);
        a2 = fmaf(wv, hp[lane + 64], a2);
        i++;
    }
    for (; i + 3 < e; i += 4) {
        const int4 pa = *(const int4*)&g_e[i];       // edges i, i+1
        const int4 pb = *(const int4*)&g_e[i + 2];   // edges i+2, i+3
        const float* h0 = &g_h[(size_t)pa.x * DF];
        const float* h1 = &g_h[(size_t)pa.z * DF];
        const float* h2 = &g_h[(size_t)pb.x * DF];
        const float* h3 = &g_h[(size_t)pb.z * DF];
        float p00 = h0[lane], p01 = h0[lane + 32], p02 = h0[lane + 64];
        float p10 = h1[lane], p11 = h1[lane + 32], p12 = h1[lane + 64];
        float p20 = h2[lane], p21 = h2[lane + 32], p22 = h2[lane + 64];
        float p30 = h3[lane], p31 = h3[lane + 32], p32 = h3[lane + 64];
        const float w0 = __int_as_float(pa.y);
        const float w1 = __int_as_float(pa.w);
        const float w2 = __int_as_float(pb.y);
        const float w3 = __int_as_float(pb.w);
        a0 = fmaf(w0, p00, a0); a1 = fmaf(w0, p01, a1); a2 = fmaf(w0, p02, a2);
        a0 = fmaf(w1, p10, a0); a1 = fmaf(w1, p11, a1); a2 = fmaf(w1, p12, a2);
        a0 = fmaf(w2, p20, a0); a1 = fmaf(w2, p21, a1); a2 = fmaf(w2, p22, a2);
        a0 = fmaf(w3, p30, a0); a1 = fmaf(w3, p31, a1); a2 = fmaf(w3, p32, a2);
    }
    for (; i < e; i++) {
        const int2 e0 = g_e[i];
        const float wv = __int_as_float(e0.y);
        const float* hp = &g_h[(size_t)e0.x * DF];
        a0 = fmaf(wv, hp[lane],      a0);
        a1 = fmaf(wv, hp[lane + 32], a1);
        a2 = fmaf(wv, hp[lane + 64], a2);
    }

    float* pre = out;
    float* act = out + (size_t)N * DF;
    const int o = gwarp * DF + lane;
    pre[o]      = a0;
    pre[o + 32] = a1;
    pre[o + 64] = a2;
    act[o]      = (a0 > 0.f) ? a0 : expm1f(a0);
    act[o + 32] = (a1 > 0.f) ? a1 : expm1f(a1);
    act[o + 64] = (a2 > 0.f) ? a2 : expm1f(a2);
}

// ---------------- launch ----------------
extern "C" void kernel_launch(void* const* d_in, const int* in_sizes, int n_in,
                              void* d_out, int out_size) {
    const float* x  = (const float*)d_in[0];
    const float* W  = (const float*)d_in[1];
    const float* b  = (const float*)d_in[2];
    const int*   ei = (const int*)d_in[3];
    const float* ew = (const float*)d_in[4];
    float* out = (float*)d_out;

    const int N = in_sizes[0] / DF;
    const int E = in_sizes[4];
    const int* row = ei;         // edge_index[0]
    const int* col = ei + E;     // edge_index[1]

    const int nAllocBlocks = (N + SCAN_E - 1) / SCAN_E;   // 49 for N=50000

    // One-time side-stream + events (created during the uncaptured
    // correctness call; no device memory allocated anywhere).
    static cudaStream_t s_side = nullptr;
    static cudaEvent_t  ev_fork = nullptr, ev_join = nullptr;
    if (s_side == nullptr) {
        cudaStreamCreateWithFlags(&s_side, cudaStreamNonBlocking);
        cudaEventCreateWithFlags(&ev_fork, cudaEventDisableTiming);
        cudaEventCreateWithFlags(&ev_join, cudaEventDisableTiming);
    }

    // Fork: GEMM on side stream, concurrent with edge chain.
    cudaEventRecord(ev_fork, 0);
    cudaStreamWaitEvent(s_side, ev_fork, 0);
    dim3 gblk(32, 8);
    gemm_kernel<<<(N + 31) / 32, gblk, 0, s_side>>>(x, W, b, N);
    cudaEventRecord(ev_join, s_side);

    // Edge chain on main (captured) stream. g_cnt/g_total zero on entry
    // (module-load init; restored every call by alloc/gather).
    hist_kernel<<<592, 256>>>(row, E);
    alloc_kernel<<<nAllocBlocks, SCAN_T>>>(N);
    scatter_kernel<<<592, 256>>>(row, col, ew, E);

    // Join: gather needs both g_h (GEMM) and the CSR (edge chain).
    cudaStreamWaitEvent(0, ev_join, 0);
    const int threads = 256;
    gather_kernel<<<((size_t)N * 32 + threads - 1) / threads, threads>>>(out, N);
}

// round 13
// speedup vs baseline: 1.4461x; 1.0086x over previous
#include <cuda_runtime.h>
#include <cuda_fp16.h>
#include <math.h>

#define NMAX 50000
#define EMAX 800000
#define DF   96
// alloc: 256 threads x 4 elems = 1024 elems per block
#define SCAN_T 256
#define SCAN_E 1024

// Scratch (allocation-free: __device__ globals). 16B-aligned for int4 access.
__device__ __align__(16) __half g_h16[NMAX * DF];  // projected features (fp16)
__device__ __align__(16) int   g_cnt[NMAX];        // per-row degree (zero at entry)
__device__ __align__(16) int   g_start[NMAX];      // row slot-range start
__device__ __align__(16) int   g_len[NMAX];        // row slot-range length
__device__ __align__(16) int   g_cur[NMAX];        // scatter cursors
__device__ int g_total;                            // slot allocator (zero at entry)
__device__ __align__(16) int2  g_e[EMAX];          // packed (col, w-bits) per slot

// ---------------- dense projection: h = x @ W + b (fp16 output) ----------
// blockDim = (32, 8). Block tile: 32 rows x 96 cols. Thread: 4 rows x 3 cols.
__global__ void gemm_kernel(const float* __restrict__ x,
                            const float* __restrict__ W,
                            const float* __restrict__ b,
                            int N) {
    __shared__ float Ws[DF * DF];      // 36 KB
    __shared__ float xs[32][DF];       // 12 KB

    const int tx  = threadIdx.x;
    const int ty  = threadIdx.y;
    const int tid = ty * 32 + tx;

    for (int i = tid; i < DF * DF; i += 256) Ws[i] = W[i];

    const float b0 = b[tx];
    const float b1 = b[tx + 32];
    const float b2 = b[tx + 64];

    const int tile = blockIdx.x * 32;
    if (tile >= N) return;

    for (int i = tid; i < 32 * DF; i += 256) {
        int r = i / DF, c = i % DF;
        int gr = tile + r;
        xs[r][c] = (gr < N) ? x[(size_t)gr * DF + c] : 0.0f;
    }
    __syncthreads();

    const int r0 = ty * 4;
    float a[4][3];
#pragma unroll
    for (int j = 0; j < 4; j++) { a[j][0] = 0.f; a[j][1] = 0.f; a[j][2] = 0.f; }

#pragma unroll 4
    for (int k = 0; k < DF; k++) {
        float w0 = Ws[k * DF + tx];
        float w1 = Ws[k * DF + tx + 32];
        float w2 = Ws[k * DF + tx + 64];
#pragma unroll
        for (int j = 0; j < 4; j++) {
            float xv = xs[r0 + j][k];
            a[j][0] = fmaf(xv, w0, a[j][0]);
            a[j][1] = fmaf(xv, w1, a[j][1]);
            a[j][2] = fmaf(xv, w2, a[j][2]);
        }
    }

#pragma unroll
    for (int j = 0; j < 4; j++) {
        int gr = tile + r0 + j;
        if (gr < N) {
            __half* hp = &g_h16[(size_t)gr * DF];
            hp[tx]      = __float2half(a[j][0] + b0);
            hp[tx + 32] = __float2half(a[j][1] + b1);
            hp[tx + 64] = __float2half(a[j][2] + b2);
        }
    }
}

// ---------------- degree histogram (x8 unroll, int4 reads) ----------------
// g_cnt is zero on entry (module-load init / restored by alloc each call).
__global__ void hist_kernel(const int* __restrict__ row, int E) {
    const int E8 = E >> 3;
    const int4* r4 = (const int4*)row;
    for (int i = blockIdx.x * blockDim.x + threadIdx.x; i < E8;
         i += gridDim.x * blockDim.x) {
        int4 va = r4[2 * i];
        int4 vb = r4[2 * i + 1];
        atomicAdd(&g_cnt[va.x], 1);
        atomicAdd(&g_cnt[va.y], 1);
        atomicAdd(&g_cnt[va.z], 1);
        atomicAdd(&g_cnt[va.w], 1);
        atomicAdd(&g_cnt[vb.x], 1);
        atomicAdd(&g_cnt[vb.y], 1);
        atomicAdd(&g_cnt[vb.z], 1);
        atomicAdd(&g_cnt[vb.w], 1);
    }
    for (int i = (E8 << 3) + blockIdx.x * blockDim.x + threadIdx.x; i < E;
         i += gridDim.x * blockDim.x) {
        atomicAdd(&g_cnt[row[i]], 1);
    }
}

// ---------------- slot allocation: block scan + one global atomicAdd -----
__global__ void alloc_kernel(int n) {
    __shared__ int warpsum[8];
    __shared__ int s_base;
    const int tid  = threadIdx.x;            // 0..255
    const int lane = tid & 31;
    const int wid  = tid >> 5;
    const int e0   = blockIdx.x * SCAN_E + tid * 4;

    int4 v;
    v.x = (e0     < n) ? g_cnt[e0]     : 0;
    v.y = (e0 + 1 < n) ? g_cnt[e0 + 1] : 0;
    v.z = (e0 + 2 < n) ? g_cnt[e0 + 2] : 0;
    v.w = (e0 + 3 < n) ? g_cnt[e0 + 3] : 0;
    const int tsum = v.x + v.y + v.z + v.w;

    int inc = tsum;
#pragma unroll
    for (int d = 1; d < 32; d <<= 1) {
        int t = __shfl_up_sync(0xFFFFFFFFu, inc, d);
        if (lane >= d) inc += t;
    }
    if (lane == 31) warpsum[wid] = inc;
    __syncthreads();
    if (tid < 8) {
        int ws = warpsum[tid];
#pragma unroll
        for (int d = 1; d < 8; d <<= 1) {
            int t = __shfl_up_sync(0xFFu, ws, d);
            if ((tid & 7) >= d) ws += t;
        }
        warpsum[tid] = ws;
    }
    __syncthreads();

    if (tid == 0) s_base = atomicAdd(&g_total, warpsum[7]);  // block base
    __syncthreads();

    const int base = s_base + ((wid > 0) ? warpsum[wid - 1] : 0) + inc - tsum;
    const int4 z = make_int4(0, 0, 0, 0);

    if (e0 + 3 < n) {
        int4 o;
        o.x = base;
        o.y = base + v.x;
        o.z = o.y + v.y;
        o.w = o.z + v.z;
        *(int4*)&g_start[e0] = o;
        *(int4*)&g_cur[e0]   = o;
        *(int4*)&g_len[e0]   = v;
        *(int4*)&g_cnt[e0]   = z;        // restore invariant for next call
    } else {
        int run = base;
#pragma unroll
        for (int j = 0; j < 4; j++) {
            int i = e0 + j;
            int c = (j == 0) ? v.x : (j == 1) ? v.y : (j == 2) ? v.z : v.w;
            if (i < n) {
                g_start[i] = run;
                g_cur[i]   = run;
                g_len[i]   = c;
                g_cnt[i]   = 0;
                run += c;
            }
        }
    }
}

// ---------------- bucket scatter (x8 unroll: 8 atomic chains in flight) ---
__global__ void scatter_kernel(const int* __restrict__ row,
                               const int* __restrict__ col,
                               const float* __restrict__ w, int E) {
    const int E8 = E >> 3;
    const int4*   r4 = (const int4*)row;
    const int4*   c4 = (const int4*)col;
    const float4* w4 = (const float4*)w;
    for (int i = blockIdx.x * blockDim.x + threadIdx.x; i < E8;
         i += gridDim.x * blockDim.x) {
        int4   ra = r4[2 * i],     rb = r4[2 * i + 1];
        int4   ca = c4[2 * i],     cb = c4[2 * i + 1];
        float4 wa = w4[2 * i],     wb = w4[2 * i + 1];
        // issue all 8 atomics first -> 8 outstanding returns
        int p0 = atomicAdd(&g_cur[ra.x], 1);
        int p1 = atomicAdd(&g_cur[ra.y], 1);
        int p2 = atomicAdd(&g_cur[ra.z], 1);
        int p3 = atomicAdd(&g_cur[ra.w], 1);
        int p4 = atomicAdd(&g_cur[rb.x], 1);
        int p5 = atomicAdd(&g_cur[rb.y], 1);
        int p6 = atomicAdd(&g_cur[rb.z], 1);
        int p7 = atomicAdd(&g_cur[rb.w], 1);
        g_e[p0] = make_int2(ca.x, __float_as_int(wa.x));
        g_e[p1] = make_int2(ca.y, __float_as_int(wa.y));
        g_e[p2] = make_int2(ca.z, __float_as_int(wa.z));
        g_e[p3] = make_int2(ca.w, __float_as_int(wa.w));
        g_e[p4] = make_int2(cb.x, __float_as_int(wb.x));
        g_e[p5] = make_int2(cb.y, __float_as_int(wb.y));
        g_e[p6] = make_int2(cb.z, __float_as_int(wb.z));
        g_e[p7] = make_int2(cb.w, __float_as_int(wb.w));
    }
    for (int i = (E8 << 3) + blockIdx.x * blockDim.x + threadIdx.x; i < E;
         i += gridDim.x * blockDim.x) {
        int p = atomicAdd(&g_cur[row[i]], 1);
        g_e[p] = make_int2(col[i], __float_as_int(w[i]));
    }
}

// ---------------- warp-per-row gather (fp16 h, fp32 accum) + ELU ---------
__global__ void gather_kernel(float* __restrict__ out, int N) {
    // reset slot allocator for the next replay (not read by this kernel)
    if (blockIdx.x == 0 && threadIdx.x == 0) g_total = 0;

    const int gwarp = (blockIdx.x * blockDim.x + threadIdx.x) >> 5;
    const int lane  = threadIdx.x & 31;
    if (gwarp >= N) return;

    const int s = g_start[gwarp];
    const int e = s + g_len[gwarp];

    float a0 = 0.f, a1 = 0.f, a2 = 0.f;
    int i = s;

    // head: align i to even so int4 pair-loads of g_e are 16B-aligned
    if ((i & 1) && i < e) {
        const int2 e0 = g_e[i];
        const float wv = __int_as_float(e0.y);
        const __half* hp = &g_h16[(size_t)e0.x * DF];
        a0 = fmaf(wv, __half2float(hp[lane]),      a0);
        a1 = fmaf(wv, __half2float(hp[lane + 32]), a1);
        a2 = fmaf(wv, __half2float(hp[lane + 64]), a2);
        i++;
    }
    for (; i + 3 < e; i += 4) {
        const int4 pa = *(const int4*)&g_e[i];       // edges i, i+1
        const int4 pb = *(const int4*)&g_e[i + 2];   // edges i+2, i+3
        const __half* h0 = &g_h16[(size_t)pa.x * DF];
        const __half* h1 = &g_h16[(size_t)pa.z * DF];
        const __half* h2 = &g_h16[(size_t)pb.x * DF];
        const __half* h3 = &g_h16[(size_t)pb.z * DF];
        __half p00 = h0[lane], p01 = h0[lane + 32], p02 = h0[lane + 64];
        __half p10 = h1[lane], p11 = h1[lane + 32], p12 = h1[lane + 64];
        __half p20 = h2[lane], p21 = h2[lane + 32], p22 = h2[lane + 64];
        __half p30 = h3[lane], p31 = h3[lane + 32], p32 = h3[lane + 64];
        const float w0 = __int_as_float(pa.y);
        const float w1 = __int_as_float(pa.w);
        const float w2 = __int_as_float(pb.y);
        const float w3 = __int_as_float(pb.w);
        a0 = fmaf(w0, __half2float(p00), a0);
        a1 = fmaf(w0, __half2float(p01), a1);
        a2 = fmaf(w0, __half2float(p02), a2);
        a0 = fmaf(w1, __half2float(p10), a0);
        a1 = fmaf(w1, __half2float(p11), a1);
        a2 = fmaf(w1, __half2float(p12), a2);
        a0 = fmaf(w2, __half2float(p20), a0);
        a1 = fmaf(w2, __half2float(p21), a1);
        a2 = fmaf(w2, __half2float(p22), a2);
        a0 = fmaf(w3, __half2float(p30), a0);
        a1 = fmaf(w3, __half2float(p31), a1);
        a2 = fmaf(w3, __half2float(p32), a2);
    }
    for (; i < e; i++) {
        const int2 e0 = g_e[i];
        const float wv = __int_as_float(e0.y);
        const __half* hp = &g_h16[(size_t)e0.x * DF];
        a0 = fmaf(wv, __half2float(hp[lane]),      a0);
        a1 = fmaf(wv, __half2float(hp[lane + 32]), a1);
        a2 = fmaf(wv, __half2float(hp[lane + 64]), a2);
    }

    float* pre = out;
    float* act = out + (size_t)N * DF;
    const int o = gwarp * DF + lane;
    pre[o]      = a0;
    pre[o + 32] = a1;
    pre[o + 64] = a2;
    act[o]      = (a0 > 0.f) ? a0 : expm1f(a0);
    act[o + 32] = (a1 > 0.f) ? a1 : expm1f(a1);
    act[o + 64] = (a2 > 0.f) ? a2 : expm1f(a2);
}

// ---------------- launch ----------------
extern "C" void kernel_launch(void* const* d_in, const int* in_sizes, int n_in,
                              void* d_out, int out_size) {
    const float* x  = (const float*)d_in[0];
    const float* W  = (const float*)d_in[1];
    const float* b  = (const float*)d_in[2];
    const int*   ei = (const int*)d_in[3];
    const float* ew = (const float*)d_in[4];
    float* out = (float*)d_out;

    const int N = in_sizes[0] / DF;
    const int E = in_sizes[4];
    const int* row = ei;         // edge_index[0]
    const int* col = ei + E;     // edge_index[1]

    const int nAllocBlocks = (N + SCAN_E - 1) / SCAN_E;   // 49 for N=50000

    // One-time side-stream + events (created during the uncaptured
    // correctness call; no device memory allocated anywhere).
    static cudaStream_t s_side = nullptr;
    static cudaEvent_t  ev_fork = nullptr, ev_join = nullptr;
    if (s_side == nullptr) {
        cudaStreamCreateWithFlags(&s_side, cudaStreamNonBlocking);
        cudaEventCreateWithFlags(&ev_fork, cudaEventDisableTiming);
        cudaEventCreateWithFlags(&ev_join, cudaEventDisableTiming);
    }

    // Fork: GEMM on side stream, concurrent with edge chain.
    cudaEventRecord(ev_fork, 0);
    cudaStreamWaitEvent(s_side, ev_fork, 0);
    dim3 gblk(32, 8);
    gemm_kernel<<<(N + 31) / 32, gblk, 0, s_side>>>(x, W, b, N);
    cudaEventRecord(ev_join, s_side);

    // Edge chain on main (captured) stream. g_cnt/g_total zero on entry
    // (module-load init; restored every call by alloc/gather).
    hist_kernel<<<400, 256>>>(row, E);
    alloc_kernel<<<nAllocBlocks, SCAN_T>>>(N);
    scatter_kernel<<<400, 256>>>(row, col, ew, E);

    // Join: gather needs both g_h16 (GEMM) and the CSR (edge chain).
    cudaStreamWaitEvent(0, ev_join, 0);
    const int threads = 256;
    gather_kernel<<<((size_t)N * 32 + threads - 1) / threads, threads>>>(out, N);
}